// round 2
// baseline (speedup 1.0000x reference)
#include <cuda_runtime.h>
#include <cuda_bf16.h>
#include <math.h>

// ---------------------------------------------------------------------------
// dividedSpaceTimeAttention
// B=8, NH=12, DIM=768, NP=196, NF=16, DH=64, D3=192, SEQ=3136, ROT=64
// SCALE = 1/(sqrt(64)*12) = 1/96
// ---------------------------------------------------------------------------

#define Bc    8
#define NHc   12
#define DIMc  768
#define NPc   196
#define NFc   16
#define D3c   192
#define SEQ1  3137          // SEQ+1
#define N3D   2304          // 3*DIM
#define MROWS (Bc*SEQ1)     // 25096
#define SCALEc (1.0f/96.0f)

// -------------------- static scratch (no allocations allowed) --------------
__device__ float g_Pq[MROWS * N3D];            // x@Wq+bq
__device__ float g_Pk[MROWS * N3D];            // x@Wk+bk
__device__ float g_Pv[MROWS * N3D];            // x@Wv+bv
__device__ float g_tmp[Bc * 195 * N3D];        // temporal attn result, patch-major
__device__ float g_ti [Bc * 195 * DIMc];       // tmp @ Wt + bt (unique rows)
__device__ float g_q2u[Bc * 195 * N3D];        // ti@Wq+bq
__device__ float g_k2u[Bc * 195 * N3D];        // ti@Wv+bv   (scores)
__device__ float g_v2u[Bc * 195 * N3D];        // ti@Wk+bk   (values)
__device__ float g_t2cat[Bc * 17 * N3D];       // [cls, 16 spatial outs] per batch
__device__ float g_outsmall[Bc * 17 * DIMc];   // t2cat @ Wf + bf

// -------------------- generic fp32 GEMM:  C = A(MxK) @ W(KxN) + bias -------
// Requirements: K % 8 == 0, N % 128 == 0. M arbitrary.
#define BM 128
#define BN 128
#define BKK 8
#define TM 8
#define TN 8

__global__ __launch_bounds__(256)
void sgemm_bias(const float* __restrict__ A, const float* __restrict__ W,
                const float* __restrict__ bias, float* __restrict__ C,
                int M, int N, int K)
{
    __shared__ float As[BKK][BM];
    __shared__ float Bs[BKK][BN];

    const int tid = threadIdx.x;
    const int bn = blockIdx.x * BN;
    const int bm = blockIdx.y * BM;
    const int tx = tid & 15;    // 0..15  (N dir)
    const int ty = tid >> 4;    // 0..15  (M dir)

    const int arow = tid >> 1;          // 0..127
    const int acol = (tid & 1) * 4;     // 0 or 4
    const int brow = tid >> 5;          // 0..7
    const int bcol = (tid & 31) * 4;    // 0..124

    float acc[TM][TN];
    #pragma unroll
    for (int i = 0; i < TM; i++)
        #pragma unroll
        for (int j = 0; j < TN; j++) acc[i][j] = 0.f;

    for (int k0 = 0; k0 < K; k0 += BKK) {
        float4 av;
        const int gr = bm + arow;
        if (gr < M) av = *reinterpret_cast<const float4*>(&A[(size_t)gr * K + k0 + acol]);
        else        av = make_float4(0.f, 0.f, 0.f, 0.f);
        As[acol + 0][arow] = av.x;
        As[acol + 1][arow] = av.y;
        As[acol + 2][arow] = av.z;
        As[acol + 3][arow] = av.w;

        const float4 bv4 = *reinterpret_cast<const float4*>(&W[(size_t)(k0 + brow) * N + bn + bcol]);
        *reinterpret_cast<float4*>(&Bs[brow][bcol]) = bv4;
        __syncthreads();

        #pragma unroll
        for (int kk = 0; kk < BKK; kk++) {
            float ra[TM], rb[TN];
            #pragma unroll
            for (int i = 0; i < TM; i++) ra[i] = As[kk][ty * TM + i];
            #pragma unroll
            for (int j = 0; j < TN; j++) rb[j] = Bs[kk][tx * TN + j];
            #pragma unroll
            for (int i = 0; i < TM; i++)
                #pragma unroll
                for (int j = 0; j < TN; j++) acc[i][j] += ra[i] * rb[j];
        }
        __syncthreads();
    }

    #pragma unroll
    for (int i = 0; i < TM; i++) {
        const int r = bm + ty * TM + i;
        if (r >= M) continue;
        #pragma unroll
        for (int j = 0; j < TN; j += 4) {
            const int c = bn + tx * TN + j;
            float4 o;
            o.x = acc[i][j + 0] + bias[c + 0];
            o.y = acc[i][j + 1] + bias[c + 1];
            o.z = acc[i][j + 2] + bias[c + 2];
            o.w = acc[i][j + 3] + bias[c + 3];
            *reinterpret_cast<float4*>(&C[(size_t)r * N + c]) = o;
        }
    }
}

// -------------------- temporal attention (per batch, head, patch) ----------
// q = rope(Pq[body]), k = rope(Pv[body]), v = Pk[body]   (crossed, per ref)
// For patch p in 1..195: 16x16 attention over frames, output summed over f.
__global__ __launch_bounds__(256)
void temporal_kernel(const float* __restrict__ Pq, const float* __restrict__ Pk,
                     const float* __restrict__ Pv, float* __restrict__ tmpf)
{
    const int p = blockIdx.x + 1;            // patch 1..195
    const int b = blockIdx.y / NHc;
    const int h = blockIdx.y % NHc;
    const int tid = threadIdx.x;

    __shared__ float qs[NFc][D3c + 1];
    __shared__ float ks[NFc][D3c + 1];
    __shared__ float vs[NFc][D3c + 1];
    __shared__ float logits[NFc][NFc + 1];
    __shared__ float colw[NFc];

    // load + rope (pairs)
    for (int e = tid; e < NFc * 96; e += 256) {
        const int f = e / 96;
        const int i = e % 96;
        const int t = f * NPc + p;                       // position in body
        const size_t base = ((size_t)(b * SEQ1 + 1 + t)) * N3D + h * D3c + 2 * i;
        float q0 = Pq[base], q1 = Pq[base + 1];
        float k0 = Pv[base], k1 = Pv[base + 1];
        const float v0 = Pk[base], v1 = Pk[base + 1];
        if (i < 32) {
            const double invf = pow(10000.0, -(double)(2 * i) / 64.0);
            const double a = (double)t * invf;
            const float c = (float)cos(a);
            const float s = (float)sin(a);
            const float nq0 = q0 * c - q1 * s, nq1 = q1 * c + q0 * s;
            const float nk0 = k0 * c - k1 * s, nk1 = k1 * c + k0 * s;
            q0 = nq0; q1 = nq1; k0 = nk0; k1 = nk1;
        }
        qs[f][2 * i] = q0; qs[f][2 * i + 1] = q1;
        ks[f][2 * i] = k0; ks[f][2 * i + 1] = k1;
        vs[f][2 * i] = v0; vs[f][2 * i + 1] = v1;
    }
    __syncthreads();

    {   // logits: thread (f,g)
        const int f = tid >> 4, g = tid & 15;
        float d = 0.f;
        #pragma unroll 8
        for (int e = 0; e < D3c; e++) d += qs[f][e] * ks[g][e];
        logits[f][g] = d * SCALEc;
    }
    __syncthreads();

    if (tid < NFc) {        // softmax per query frame f
        const int f = tid;
        float m = -1e30f;
        #pragma unroll
        for (int g = 0; g < NFc; g++) m = fmaxf(m, logits[f][g]);
        float l = 0.f;
        #pragma unroll
        for (int g = 0; g < NFc; g++) l += expf(logits[f][g] - m);
        const float inv = 1.f / l;
        #pragma unroll
        for (int g = 0; g < NFc; g++) logits[f][g] = expf(logits[f][g] - m) * inv;
    }
    __syncthreads();

    if (tid < NFc) {        // column weights: sum over f
        const int g = tid;
        float s = 0.f;
        #pragma unroll
        for (int f = 0; f < NFc; f++) s += logits[f][g];
        colw[g] = s;
    }
    __syncthreads();

    if (tid < D3c) {
        const int d = tid;
        float a = 0.f;
        #pragma unroll
        for (int g = 0; g < NFc; g++) a += colw[g] * vs[g][d];
        tmpf[((size_t)(b * 195 + (p - 1))) * N3D + h * D3c + d] = a;
    }
}

// -------------------- cls attention (1 query over all 3137 keys) -----------
__global__ __launch_bounds__(256)
void cls_kernel(const float* __restrict__ Pq, const float* __restrict__ Pk,
                const float* __restrict__ Pv, float* __restrict__ t2cat)
{
    const int b = blockIdx.x / NHc;
    const int h = blockIdx.x % NHc;
    const int tid = threadIdx.x;

    __shared__ float logits[SEQ1];
    __shared__ float qv[D3c];
    __shared__ float red[256];

    if (tid < D3c) qv[tid] = Pq[((size_t)(b * SEQ1)) * N3D + h * D3c + tid];
    __syncthreads();

    float lmax = -1e30f;
    for (int s = tid; s < SEQ1; s += 256) {
        const float* kr = Pk + ((size_t)(b * SEQ1 + s)) * N3D + h * D3c;
        float d = 0.f;
        #pragma unroll 8
        for (int e = 0; e < D3c; e++) d += qv[e] * kr[e];
        d *= SCALEc;
        logits[s] = d;
        lmax = fmaxf(lmax, d);
    }
    red[tid] = lmax; __syncthreads();
    for (int o = 128; o > 0; o >>= 1) { if (tid < o) red[tid] = fmaxf(red[tid], red[tid + o]); __syncthreads(); }
    const float M = red[0];
    __syncthreads();

    float lsum = 0.f;
    for (int s = tid; s < SEQ1; s += 256) {
        const float w = expf(logits[s] - M);
        logits[s] = w;
        lsum += w;
    }
    red[tid] = lsum; __syncthreads();
    for (int o = 128; o > 0; o >>= 1) { if (tid < o) red[tid] += red[tid + o]; __syncthreads(); }
    const float inv = 1.f / red[0];
    __syncthreads();

    if (tid < D3c) {
        float a = 0.f;
        for (int s = 0; s < SEQ1; s++)
            a += logits[s] * Pv[((size_t)(b * SEQ1 + s)) * N3D + h * D3c + tid];
        t2cat[((size_t)(b * 17)) * N3D + h * D3c + tid] = a * inv;
    }
}

// -------------------- spatial attention over unique ti rows ----------------
// xi=0: 196 queries (patch (j)%195) x 196 keys (patch m%195)
// xi>0: 196 queries (patch (xi+j)%195) x 16 keys (patch (xi+m)%195)
// scores vs k2u (Wv proj), values from v2u (Wk proj). Sum over queries.
__global__ __launch_bounds__(256)
void spatial_kernel(const float* __restrict__ q2u, const float* __restrict__ k2u,
                    const float* __restrict__ v2u, float* __restrict__ t2cat)
{
    const int xi = blockIdx.x;               // 0..15
    const int b = blockIdx.y / NHc;
    const int h = blockIdx.y % NHc;
    const int tid = threadIdx.x;
    const int warp = tid >> 5, lane = tid & 31;
    const int nk = (xi == 0) ? 196 : 16;
    const int hb = h * D3c;

    __shared__ float wsh[8][200];
    __shared__ float wacc[8][D3c];

    for (int e = tid; e < 8 * D3c; e += 256) wacc[e / D3c][e % D3c] = 0.f;
    __syncthreads();

    for (int q0 = warp; q0 < 196; q0 += 8) {
        const int qp = (xi + q0) % 195;
        const float* qr = q2u + ((size_t)(b * 195 + qp)) * N3D + hb;

        float lg[7];
        float lmax = -1e30f;
        int cnt = 0;
        for (int m = lane; m < nk; m += 32) {
            const int kp = (xi == 0) ? (m % 195) : ((xi + m) % 195);
            const float* kr = k2u + ((size_t)(b * 195 + kp)) * N3D + hb;
            float d = 0.f;
            #pragma unroll 8
            for (int e = 0; e < D3c; e++) d += qr[e] * kr[e];
            lg[cnt++] = d * SCALEc;
            lmax = fmaxf(lmax, d * SCALEc);
        }
        #pragma unroll
        for (int o = 16; o > 0; o >>= 1) lmax = fmaxf(lmax, __shfl_xor_sync(0xffffffffu, lmax, o));
        float lsum = 0.f;
        for (int c = 0; c < cnt; c++) { lg[c] = expf(lg[c] - lmax); lsum += lg[c]; }
        #pragma unroll
        for (int o = 16; o > 0; o >>= 1) lsum += __shfl_xor_sync(0xffffffffu, lsum, o);
        const float inv = 1.f / lsum;
        cnt = 0;
        for (int m = lane; m < nk; m += 32) wsh[warp][m] = lg[cnt++] * inv;
        __syncwarp();

        for (int dd = lane; dd < D3c; dd += 32) {
            float a = 0.f;
            for (int m = 0; m < nk; m++) {
                const int kp = (xi == 0) ? (m % 195) : ((xi + m) % 195);
                a += wsh[warp][m] * v2u[((size_t)(b * 195 + kp)) * N3D + hb + dd];
            }
            wacc[warp][dd] += a;   // warp-private, race-free
        }
        __syncwarp();
    }
    __syncthreads();

    if (tid < D3c) {
        float s = 0.f;
        #pragma unroll
        for (int wp = 0; wp < 8; wp++) s += wacc[wp][tid];
        t2cat[((size_t)(b * 17) + 1 + xi) * N3D + hb + tid] = s;
    }
}

// -------------------- broadcast final rows ---------------------------------
__global__ void broadcast_kernel(const float* __restrict__ outsmall, float* __restrict__ out)
{
    const size_t i = (size_t)blockIdx.x * blockDim.x + threadIdx.x;
    const size_t total = (size_t)Bc * SEQ1 * DIMc;
    if (i >= total) return;
    const int c = (int)(i % DIMc);
    const size_t bs = i / DIMc;
    const int s = (int)(bs % SEQ1);
    const int b = (int)(bs / SEQ1);
    const int r = (s == 0) ? 0 : (1 + ((s - 1) & 15));
    out[i] = outsmall[((size_t)(b * 17) + r) * DIMc + c];
}

// -------------------- launch -----------------------------------------------
extern "C" void kernel_launch(void* const* d_in, const int* in_sizes, int n_in,
                              void* d_out, int out_size)
{
    const float* x  = (const float*)d_in[0];
    const float* Wq = (const float*)d_in[1];
    const float* bq = (const float*)d_in[2];
    const float* Wk = (const float*)d_in[3];
    const float* bk = (const float*)d_in[4];
    const float* Wv = (const float*)d_in[5];
    const float* bv = (const float*)d_in[6];
    const float* Wt = (const float*)d_in[7];
    const float* bt = (const float*)d_in[8];
    const float* Wf = (const float*)d_in[9];
    const float* bf = (const float*)d_in[10];
    float* out = (float*)d_out;

    float *Pq, *Pk, *Pv, *tmpf, *ti, *q2u, *k2u, *v2u, *t2cat, *outsmall;
    cudaGetSymbolAddress((void**)&Pq, g_Pq);
    cudaGetSymbolAddress((void**)&Pk, g_Pk);
    cudaGetSymbolAddress((void**)&Pv, g_Pv);
    cudaGetSymbolAddress((void**)&tmpf, g_tmp);
    cudaGetSymbolAddress((void**)&ti, g_ti);
    cudaGetSymbolAddress((void**)&q2u, g_q2u);
    cudaGetSymbolAddress((void**)&k2u, g_k2u);
    cudaGetSymbolAddress((void**)&v2u, g_v2u);
    cudaGetSymbolAddress((void**)&t2cat, g_t2cat);
    cudaGetSymbolAddress((void**)&outsmall, g_outsmall);

    const dim3 blk(256);

    // 1) QKV projections over all 25096 rows (dominant cost)
    {
        const dim3 g(N3D / BN, (MROWS + BM - 1) / BM);
        sgemm_bias<<<g, blk>>>(x, Wq, bq, Pq, MROWS, N3D, DIMc);
        sgemm_bias<<<g, blk>>>(x, Wk, bk, Pk, MROWS, N3D, DIMc);
        sgemm_bias<<<g, blk>>>(x, Wv, bv, Pv, MROWS, N3D, DIMc);
    }

    // 2) temporal attention over frames (patches 1..195)
    temporal_kernel<<<dim3(195, Bc * NHc), blk>>>(Pq, Pk, Pv, tmpf);

    // 3) cls attention -> t2cat row 0 per batch
    cls_kernel<<<Bc * NHc, blk>>>(Pq, Pk, Pv, t2cat);

    // 4) ti = tmp @ Wt + bt   (only 195 unique rows per batch)
    sgemm_bias<<<dim3(DIMc / BN, (Bc * 195 + BM - 1) / BM), blk>>>(tmpf, Wt, bt, ti, Bc * 195, DIMc, N3D);

    // 5) second-stage projections on unique ti rows
    {
        const dim3 g(N3D / BN, (Bc * 195 + BM - 1) / BM);
        sgemm_bias<<<g, blk>>>(ti, Wq, bq, q2u, Bc * 195, N3D, DIMc);
        sgemm_bias<<<g, blk>>>(ti, Wv, bv, k2u, Bc * 195, N3D, DIMc);  // scores
        sgemm_bias<<<g, blk>>>(ti, Wk, bk, v2u, Bc * 195, N3D, DIMc);  // values
    }

    // 6) spatial attention -> t2cat rows 1..16 per batch
    spatial_kernel<<<dim3(16, Bc * NHc), blk>>>(q2u, k2u, v2u, t2cat);

    // 7) final projection of the 17 unique rows per batch
    sgemm_bias<<<dim3(DIMc / BN, (Bc * 17 + BM - 1) / BM), blk>>>(t2cat, Wf, bf, outsmall, Bc * 17, DIMc, N3D);

    // 8) broadcast to full (8, 3137, 768) output
    {
        const size_t total = (size_t)Bc * SEQ1 * DIMc;
        broadcast_kernel<<<(unsigned)((total + 255) / 256), blk>>>(outsmall, out);
    }
}

// round 5
// speedup vs baseline: 1.1980x; 1.1980x over previous
#include <cuda_runtime.h>
#include <cuda_bf16.h>
#include <math.h>
#include <stdint.h>

// ---------------------------------------------------------------------------
// dividedSpaceTimeAttention — mma.sync split-bf16 GEMM version
// (tcgen05 unavailable: harness compiles PTX for compute_103, not 103a)
// B=8, NH=12, DIM=768, NP=196, NF=16, DH=64, D3=192, SEQ=3136, ROT=64
// ---------------------------------------------------------------------------

#define Bc    8
#define NHc   12
#define DIMc  768
#define NPc   196
#define NFc   16
#define D3c   192
#define SEQ1  3137
#define N3D   2304
#define MROWS (Bc*SEQ1)     // 25096
#define SCALEc (1.0f/96.0f)

// -------------------- static scratch ---------------------------------------
__device__ float g_Pq[MROWS * N3D];
__device__ float g_Pk[MROWS * N3D];
__device__ float g_Pv[MROWS * N3D];
__device__ float g_tmp[Bc * 195 * N3D];
__device__ float g_ti [Bc * 195 * DIMc];
__device__ float g_q2u[Bc * 195 * N3D];
__device__ float g_k2u[Bc * 195 * N3D];
__device__ float g_v2u[Bc * 195 * N3D];
__device__ float g_t2cat[Bc * 17 * N3D];
__device__ float g_outsmall[Bc * 17 * DIMc];
// transposed weights: WT[n][k] row-major (K-major rows)
__device__ float g_WqT[N3D * DIMc];
__device__ float g_WkT[N3D * DIMc];
__device__ float g_WvT[N3D * DIMc];
__device__ float g_WtT[DIMc * N3D];
__device__ float g_WfT[DIMc * N3D];

__device__ __forceinline__ uint32_t smem_u32(const void* p) {
    uint32_t a;
    asm("{ .reg .u64 t; cvta.to.shared.u64 t, %1; cvt.u32.u64 %0, t; }" : "=r"(a) : "l"(p));
    return a;
}

// ===================== transpose: W[K][N] -> WT[N][K] ======================
__global__ __launch_bounds__(256)
void transpose_k(const float* __restrict__ W, float* __restrict__ WT, int K, int N)
{
    __shared__ float t[32][33];
    const int k0 = blockIdx.x * 32, n0 = blockIdx.y * 32;
    const int x = threadIdx.x & 31, y = (threadIdx.x >> 5) * 4;
    #pragma unroll
    for (int j = 0; j < 4; j++) {
        const int k = k0 + y + j, n = n0 + x;
        t[y + j][x] = (k < K && n < N) ? W[(size_t)k * N + n] : 0.f;
    }
    __syncthreads();
    #pragma unroll
    for (int j = 0; j < 4; j++) {
        const int n = n0 + y + j, k = k0 + x;
        if (n < N && k < K) WT[(size_t)n * K + k] = t[x][y + j];
    }
}

// ===================== mma.sync split-bf16 GEMM ============================
// C(z) = A(MxK) @ WT(z)^T + bias(z).  Tile 128x128, BK=32, 8 warps (32x64 each).
// SMEM row pitch 80B (64B data + 16B pad) -> ldmatrix conflict-free.
#define GBM 128
#define GBN 128
#define GBK 32
#define PITCH 80
#define TILEB (128 * PITCH)          // 10240
#define OFF_AH 0
#define OFF_AL (TILEB)
#define OFF_BH (2 * TILEB)
#define OFF_BL (3 * TILEB)
#define BUFB   (4 * TILEB)           // 40960
#define GEMM_SMEM (2 * BUFB)         // 81920

__device__ __forceinline__ void ldm_x4(uint32_t* r, uint32_t addr) {
    asm volatile("ldmatrix.sync.aligned.m8n8.x4.shared.b16 {%0,%1,%2,%3}, [%4];"
                 : "=r"(r[0]), "=r"(r[1]), "=r"(r[2]), "=r"(r[3]) : "r"(addr));
}
__device__ __forceinline__ void mma_bf16(float* d, const uint32_t* a, uint32_t b0, uint32_t b1) {
    asm volatile("mma.sync.aligned.m16n8k16.row.col.f32.bf16.bf16.f32 "
                 "{%0,%1,%2,%3}, {%4,%5,%6,%7}, {%8,%9}, {%0,%1,%2,%3};"
                 : "+f"(d[0]), "+f"(d[1]), "+f"(d[2]), "+f"(d[3])
                 : "r"(a[0]), "r"(a[1]), "r"(a[2]), "r"(a[3]), "r"(b0), "r"(b1));
}

__global__ __launch_bounds__(256)
void gemm_mma(const float* __restrict__ A,
              const float* __restrict__ W0, const float* __restrict__ W1, const float* __restrict__ W2,
              const float* __restrict__ b0v, const float* __restrict__ b1v, const float* __restrict__ b2v,
              float* __restrict__ C0, float* __restrict__ C1, float* __restrict__ C2,
              int M, int N, int K)
{
    extern __shared__ char sb[];
    const uint32_t sbase = smem_u32(sb);

    const int tid = threadIdx.x;
    const int lane = tid & 31;
    const int wid = tid >> 5;
    const int wm = wid & 3;          // 4 warps in M (32 rows each)
    const int wn = wid >> 2;         // 2 warps in N (64 cols each)

    const int z = blockIdx.z;
    const float* W    = (z == 0) ? W0  : (z == 1) ? W1  : W2;
    const float* bias = (z == 0) ? b0v : (z == 1) ? b1v : b2v;
    float*       C    = (z == 0) ? C0  : (z == 1) ? C1  : C2;

    const int bm = blockIdx.y * GBM;
    const int bn = blockIdx.x * GBN;
    const int NC = K / GBK;

    // loader task mapping: s = tid + i*256 over 1024 tasks; row = s>>3, kg = s&7
    const int lrow = tid >> 3;       // base row for i=0 (rows advance by 32 per i)
    const int lkg  = tid & 7;

    float4 rA[4], rB[4];

    auto ldg_chunk = [&](int c) {
        const int k0 = c * GBK + lkg * 4;
        #pragma unroll
        for (int i = 0; i < 4; i++) {
            const int row = lrow + i * 32;
            const int gr = bm + row;
            rA[i] = (gr < M) ? *reinterpret_cast<const float4*>(&A[(size_t)gr * K + k0])
                             : make_float4(0.f, 0.f, 0.f, 0.f);
            rB[i] = *reinterpret_cast<const float4*>(&W[(size_t)(bn + row) * K + k0]);
        }
    };
    auto sts_chunk = [&](int buf) {
        char* base = sb + buf * BUFB;
        #pragma unroll
        for (int i = 0; i < 4; i++) {
            const int row = lrow + i * 32;
            const uint32_t off = (uint32_t)(row * PITCH + lkg * 8);
            {
                const float4 v = rA[i];
                __nv_bfloat162 h01 = __floats2bfloat162_rn(v.x, v.y);
                __nv_bfloat162 h23 = __floats2bfloat162_rn(v.z, v.w);
                __nv_bfloat162 l01 = __floats2bfloat162_rn(v.x - __bfloat162float(h01.x),
                                                           v.y - __bfloat162float(h01.y));
                __nv_bfloat162 l23 = __floats2bfloat162_rn(v.z - __bfloat162float(h23.x),
                                                           v.w - __bfloat162float(h23.y));
                *reinterpret_cast<uint2*>(base + OFF_AH + off) =
                    make_uint2(*reinterpret_cast<uint32_t*>(&h01), *reinterpret_cast<uint32_t*>(&h23));
                *reinterpret_cast<uint2*>(base + OFF_AL + off) =
                    make_uint2(*reinterpret_cast<uint32_t*>(&l01), *reinterpret_cast<uint32_t*>(&l23));
            }
            {
                const float4 v = rB[i];
                __nv_bfloat162 h01 = __floats2bfloat162_rn(v.x, v.y);
                __nv_bfloat162 h23 = __floats2bfloat162_rn(v.z, v.w);
                __nv_bfloat162 l01 = __floats2bfloat162_rn(v.x - __bfloat162float(h01.x),
                                                           v.y - __bfloat162float(h01.y));
                __nv_bfloat162 l23 = __floats2bfloat162_rn(v.z - __bfloat162float(h23.x),
                                                           v.w - __bfloat162float(h23.y));
                *reinterpret_cast<uint2*>(base + OFF_BH + off) =
                    make_uint2(*reinterpret_cast<uint32_t*>(&h01), *reinterpret_cast<uint32_t*>(&h23));
                *reinterpret_cast<uint2*>(base + OFF_BL + off) =
                    make_uint2(*reinterpret_cast<uint32_t*>(&l01), *reinterpret_cast<uint32_t*>(&l23));
            }
        }
    };

    float acc[2][8][4];
    #pragma unroll
    for (int i = 0; i < 2; i++)
        #pragma unroll
        for (int j = 0; j < 8; j++)
            #pragma unroll
            for (int q = 0; q < 4; q++) acc[i][j][q] = 0.f;

    // ldmatrix per-lane address components
    const uint32_t a_row_off = (uint32_t)((wm * 32 + (lane & 15)) * PITCH) + ((lane >> 4) * 16);
    const int bgrp = lane >> 3;                  // 0..3
    const uint32_t b_row = (uint32_t)(wn * 64 + (bgrp >> 1) * 8 + (lane & 7));
    const uint32_t b_kb  = (uint32_t)((bgrp & 1) * 16);

    ldg_chunk(0);
    sts_chunk(0);
    __syncthreads();

    for (int c = 0; c < NC; c++) {
        if (c + 1 < NC) ldg_chunk(c + 1);

        const uint32_t base = sbase + (uint32_t)((c & 1) * BUFB);
        #pragma unroll
        for (int ks = 0; ks < 2; ks++) {
            const uint32_t koff = (uint32_t)(ks * 32);
            uint32_t ah[2][4], al[2][4];
            #pragma unroll
            for (int mt = 0; mt < 2; mt++) {
                const uint32_t aaddr = base + a_row_off + (uint32_t)(mt * 16 * PITCH) + koff;
                ldm_x4(ah[mt], aaddr + OFF_AH);
                ldm_x4(al[mt], aaddr + OFF_AL);
            }
            #pragma unroll
            for (int pair = 0; pair < 4; pair++) {
                const uint32_t baddr = base + (b_row + (uint32_t)(pair * 16)) * PITCH + b_kb + koff;
                uint32_t bh[4], bl[4];
                ldm_x4(bh, baddr + OFF_BH);
                ldm_x4(bl, baddr + OFF_BL);
                #pragma unroll
                for (int mt = 0; mt < 2; mt++) {
                    #pragma unroll
                    for (int nt = 0; nt < 2; nt++) {
                        float* d = acc[mt][pair * 2 + nt];
                        mma_bf16(d, ah[mt], bh[nt * 2], bh[nt * 2 + 1]);
                        mma_bf16(d, ah[mt], bl[nt * 2], bl[nt * 2 + 1]);
                        mma_bf16(d, al[mt], bh[nt * 2], bh[nt * 2 + 1]);
                    }
                }
            }
        }
        __syncthreads();
        if (c + 1 < NC) {
            sts_chunk((c + 1) & 1);
            __syncthreads();
        }
    }

    // ---- epilogue ----
    #pragma unroll
    for (int mt = 0; mt < 2; mt++) {
        const int r = bm + wm * 32 + mt * 16 + (lane >> 2);
        #pragma unroll
        for (int j = 0; j < 8; j++) {
            const int col = bn + wn * 64 + j * 8 + (lane & 3) * 2;
            const float bx = bias[col], by = bias[col + 1];
            if (r < M) {
                float2 o = make_float2(acc[mt][j][0] + bx, acc[mt][j][1] + by);
                *reinterpret_cast<float2*>(&C[(size_t)r * N + col]) = o;
            }
            if (r + 8 < M) {
                float2 o = make_float2(acc[mt][j][2] + bx, acc[mt][j][3] + by);
                *reinterpret_cast<float2*>(&C[(size_t)(r + 8) * N + col]) = o;
            }
        }
    }
}

// ===================== attention kernels (passing since R2) ================
__global__ __launch_bounds__(256)
void temporal_kernel(const float* __restrict__ Pq, const float* __restrict__ Pk,
                     const float* __restrict__ Pv, float* __restrict__ tmpf)
{
    const int p = blockIdx.x + 1;
    const int b = blockIdx.y / NHc;
    const int h = blockIdx.y % NHc;
    const int tid = threadIdx.x;

    __shared__ float qs[NFc][D3c + 1];
    __shared__ float ks[NFc][D3c + 1];
    __shared__ float vs[NFc][D3c + 1];
    __shared__ float logits[NFc][NFc + 1];
    __shared__ float colw[NFc];

    for (int e = tid; e < NFc * 96; e += 256) {
        const int f = e / 96;
        const int i = e % 96;
        const int t = f * NPc + p;
        const size_t base = ((size_t)(b * SEQ1 + 1 + t)) * N3D + h * D3c + 2 * i;
        float q0 = Pq[base], q1 = Pq[base + 1];
        float k0 = Pv[base], k1 = Pv[base + 1];
        const float v0 = Pk[base], v1 = Pk[base + 1];
        if (i < 32) {
            const double invf = pow(10000.0, -(double)(2 * i) / 64.0);
            const double a = (double)t * invf;
            const float c = (float)cos(a);
            const float s = (float)sin(a);
            const float nq0 = q0 * c - q1 * s, nq1 = q1 * c + q0 * s;
            const float nk0 = k0 * c - k1 * s, nk1 = k1 * c + k0 * s;
            q0 = nq0; q1 = nq1; k0 = nk0; k1 = nk1;
        }
        qs[f][2 * i] = q0; qs[f][2 * i + 1] = q1;
        ks[f][2 * i] = k0; ks[f][2 * i + 1] = k1;
        vs[f][2 * i] = v0; vs[f][2 * i + 1] = v1;
    }
    __syncthreads();

    {
        const int f = tid >> 4, g = tid & 15;
        float d = 0.f;
        #pragma unroll 8
        for (int e = 0; e < D3c; e++) d += qs[f][e] * ks[g][e];
        logits[f][g] = d * SCALEc;
    }
    __syncthreads();

    if (tid < NFc) {
        const int f = tid;
        float m = -1e30f;
        #pragma unroll
        for (int g = 0; g < NFc; g++) m = fmaxf(m, logits[f][g]);
        float l = 0.f;
        #pragma unroll
        for (int g = 0; g < NFc; g++) l += expf(logits[f][g] - m);
        const float inv = 1.f / l;
        #pragma unroll
        for (int g = 0; g < NFc; g++) logits[f][g] = expf(logits[f][g] - m) * inv;
    }
    __syncthreads();

    if (tid < NFc) {
        const int g = tid;
        float s = 0.f;
        #pragma unroll
        for (int f = 0; f < NFc; f++) s += logits[f][g];
        colw[g] = s;
    }
    __syncthreads();

    if (tid < D3c) {
        const int d = tid;
        float a = 0.f;
        #pragma unroll
        for (int g = 0; g < NFc; g++) a += colw[g] * vs[g][d];
        tmpf[((size_t)(b * 195 + (p - 1))) * N3D + h * D3c + d] = a;
    }
}

__global__ __launch_bounds__(256)
void cls_kernel(const float* __restrict__ Pq, const float* __restrict__ Pk,
                const float* __restrict__ Pv, float* __restrict__ t2cat)
{
    const int b = blockIdx.x / NHc;
    const int h = blockIdx.x % NHc;
    const int tid = threadIdx.x;

    __shared__ float logits[SEQ1];
    __shared__ float qv[D3c];
    __shared__ float red[256];

    if (tid < D3c) qv[tid] = Pq[((size_t)(b * SEQ1)) * N3D + h * D3c + tid];
    __syncthreads();

    float lmax = -1e30f;
    for (int s = tid; s < SEQ1; s += 256) {
        const float* kr = Pk + ((size_t)(b * SEQ1 + s)) * N3D + h * D3c;
        float d = 0.f;
        #pragma unroll 8
        for (int e = 0; e < D3c; e++) d += qv[e] * kr[e];
        d *= SCALEc;
        logits[s] = d;
        lmax = fmaxf(lmax, d);
    }
    red[tid] = lmax; __syncthreads();
    for (int o = 128; o > 0; o >>= 1) { if (tid < o) red[tid] = fmaxf(red[tid], red[tid + o]); __syncthreads(); }
    const float M = red[0];
    __syncthreads();

    float lsum = 0.f;
    for (int s = tid; s < SEQ1; s += 256) {
        const float w = expf(logits[s] - M);
        logits[s] = w;
        lsum += w;
    }
    red[tid] = lsum; __syncthreads();
    for (int o = 128; o > 0; o >>= 1) { if (tid < o) red[tid] += red[tid + o]; __syncthreads(); }
    const float inv = 1.f / red[0];
    __syncthreads();

    if (tid < D3c) {
        float a = 0.f;
        for (int s = 0; s < SEQ1; s++)
            a += logits[s] * Pv[((size_t)(b * SEQ1 + s)) * N3D + h * D3c + tid];
        t2cat[((size_t)(b * 17)) * N3D + h * D3c + tid] = a * inv;
    }
}

__global__ __launch_bounds__(256)
void spatial_kernel(const float* __restrict__ q2u, const float* __restrict__ k2u,
                    const float* __restrict__ v2u, float* __restrict__ t2cat)
{
    const int xi = blockIdx.x;
    const int b = blockIdx.y / NHc;
    const int h = blockIdx.y % NHc;
    const int tid = threadIdx.x;
    const int warp = tid >> 5, lane = tid & 31;
    const int nk = (xi == 0) ? 196 : 16;
    const int hb = h * D3c;

    __shared__ float wsh[8][200];
    __shared__ float wacc[8][D3c];

    for (int e = tid; e < 8 * D3c; e += 256) wacc[e / D3c][e % D3c] = 0.f;
    __syncthreads();

    for (int q0 = warp; q0 < 196; q0 += 8) {
        const int qp = (xi + q0) % 195;
        const float* qr = q2u + ((size_t)(b * 195 + qp)) * N3D + hb;

        float lg[7];
        float lmax = -1e30f;
        int cnt = 0;
        for (int m = lane; m < nk; m += 32) {
            const int kp = (xi == 0) ? (m % 195) : ((xi + m) % 195);
            const float* kr = k2u + ((size_t)(b * 195 + kp)) * N3D + hb;
            float d = 0.f;
            #pragma unroll 8
            for (int e = 0; e < D3c; e++) d += qr[e] * kr[e];
            lg[cnt++] = d * SCALEc;
            lmax = fmaxf(lmax, d * SCALEc);
        }
        #pragma unroll
        for (int o = 16; o > 0; o >>= 1) lmax = fmaxf(lmax, __shfl_xor_sync(0xffffffffu, lmax, o));
        float lsum = 0.f;
        for (int c = 0; c < cnt; c++) { lg[c] = expf(lg[c] - lmax); lsum += lg[c]; }
        #pragma unroll
        for (int o = 16; o > 0; o >>= 1) lsum += __shfl_xor_sync(0xffffffffu, lsum, o);
        const float inv = 1.f / lsum;
        cnt = 0;
        for (int m = lane; m < nk; m += 32) wsh[warp][m] = lg[cnt++] * inv;
        __syncwarp();

        for (int dd = lane; dd < D3c; dd += 32) {
            float a = 0.f;
            for (int m = 0; m < nk; m++) {
                const int kp = (xi == 0) ? (m % 195) : ((xi + m) % 195);
                a += wsh[warp][m] * v2u[((size_t)(b * 195 + kp)) * N3D + hb + dd];
            }
            wacc[warp][dd] += a;
        }
        __syncwarp();
    }
    __syncthreads();

    if (tid < D3c) {
        float s = 0.f;
        #pragma unroll
        for (int wp = 0; wp < 8; wp++) s += wacc[wp][tid];
        t2cat[((size_t)(b * 17) + 1 + xi) * N3D + hb + tid] = s;
    }
}

__global__ void broadcast_kernel(const float* __restrict__ outsmall, float* __restrict__ out)
{
    const size_t i = (size_t)blockIdx.x * blockDim.x + threadIdx.x;
    const size_t total = (size_t)Bc * SEQ1 * DIMc;
    if (i >= total) return;
    const int c = (int)(i % DIMc);
    const size_t bs = i / DIMc;
    const int s = (int)(bs % SEQ1);
    const int b = (int)(bs / SEQ1);
    const int r = (s == 0) ? 0 : (1 + ((s - 1) & 15));
    out[i] = outsmall[((size_t)(b * 17) + r) * DIMc + c];
}

// ===================== launch ==============================================
extern "C" void kernel_launch(void* const* d_in, const int* in_sizes, int n_in,
                              void* d_out, int out_size)
{
    const float* x  = (const float*)d_in[0];
    const float* Wq = (const float*)d_in[1];
    const float* bq = (const float*)d_in[2];
    const float* Wk = (const float*)d_in[3];
    const float* bk = (const float*)d_in[4];
    const float* Wv = (const float*)d_in[5];
    const float* bv = (const float*)d_in[6];
    const float* Wt = (const float*)d_in[7];
    const float* bt = (const float*)d_in[8];
    const float* Wf = (const float*)d_in[9];
    const float* bf = (const float*)d_in[10];
    float* out = (float*)d_out;

    float *Pq, *Pk, *Pv, *tmpf, *ti, *q2u, *k2u, *v2u, *t2cat, *outsmall;
    float *WqT, *WkT, *WvT, *WtT, *WfT;
    cudaGetSymbolAddress((void**)&Pq, g_Pq);
    cudaGetSymbolAddress((void**)&Pk, g_Pk);
    cudaGetSymbolAddress((void**)&Pv, g_Pv);
    cudaGetSymbolAddress((void**)&tmpf, g_tmp);
    cudaGetSymbolAddress((void**)&ti, g_ti);
    cudaGetSymbolAddress((void**)&q2u, g_q2u);
    cudaGetSymbolAddress((void**)&k2u, g_k2u);
    cudaGetSymbolAddress((void**)&v2u, g_v2u);
    cudaGetSymbolAddress((void**)&t2cat, g_t2cat);
    cudaGetSymbolAddress((void**)&outsmall, g_outsmall);
    cudaGetSymbolAddress((void**)&WqT, g_WqT);
    cudaGetSymbolAddress((void**)&WkT, g_WkT);
    cudaGetSymbolAddress((void**)&WvT, g_WvT);
    cudaGetSymbolAddress((void**)&WtT, g_WtT);
    cudaGetSymbolAddress((void**)&WfT, g_WfT);

    cudaFuncSetAttribute(gemm_mma, cudaFuncAttributeMaxDynamicSharedMemorySize, GEMM_SMEM);

    const dim3 blk(256);

    // 0) transpose weights -> [N][K]
    transpose_k<<<dim3(DIMc / 32, N3D / 32), blk>>>(Wq, WqT, DIMc, N3D);
    transpose_k<<<dim3(DIMc / 32, N3D / 32), blk>>>(Wk, WkT, DIMc, N3D);
    transpose_k<<<dim3(DIMc / 32, N3D / 32), blk>>>(Wv, WvT, DIMc, N3D);
    transpose_k<<<dim3(N3D / 32, DIMc / 32), blk>>>(Wt, WtT, N3D, DIMc);
    transpose_k<<<dim3(N3D / 32, DIMc / 32), blk>>>(Wf, WfT, N3D, DIMc);

    // 1) QKV projections (fused 3-in-1)
    gemm_mma<<<dim3(N3D / GBN, (MROWS + GBM - 1) / GBM, 3), blk, GEMM_SMEM>>>(
        x, WqT, WkT, WvT, bq, bk, bv, Pq, Pk, Pv, MROWS, N3D, DIMc);

    // 2) temporal + cls attention
    temporal_kernel<<<dim3(195, Bc * NHc), blk>>>(Pq, Pk, Pv, tmpf);
    cls_kernel<<<Bc * NHc, blk>>>(Pq, Pk, Pv, t2cat);

    // 3) ti = tmp @ Wt + bt   (195 unique rows per batch)
    gemm_mma<<<dim3(DIMc / GBN, (Bc * 195 + GBM - 1) / GBM, 1), blk, GEMM_SMEM>>>(
        tmpf, WtT, WtT, WtT, bt, bt, bt, ti, ti, ti, Bc * 195, DIMc, N3D);

    // 4) second-stage projections (fused 3-in-1; note crossed k/v per reference)
    gemm_mma<<<dim3(N3D / GBN, (Bc * 195 + GBM - 1) / GBM, 3), blk, GEMM_SMEM>>>(
        ti, WqT, WvT, WkT, bq, bv, bk, q2u, k2u, v2u, Bc * 195, N3D, DIMc);

    // 5) spatial attention
    spatial_kernel<<<dim3(16, Bc * NHc), blk>>>(q2u, k2u, v2u, t2cat);

    // 6) final projection of 17 unique rows per batch
    gemm_mma<<<dim3(DIMc / GBN, (Bc * 17 + GBM - 1) / GBM, 1), blk, GEMM_SMEM>>>(
        t2cat, WfT, WfT, WfT, bf, bf, bf, outsmall, outsmall, outsmall, Bc * 17, DIMc, N3D);

    // 7) broadcast to full output
    const size_t total = (size_t)Bc * SEQ1 * DIMc;
    broadcast_kernel<<<(unsigned)((total + 255) / 256), blk>>>(outsmall, out);
}